// round 13
// baseline (speedup 1.0000x reference)
#include <cuda_runtime.h>
#include <cstdint>

// Problem constants
#define NM 100000
#define NT 100000
#define NE 400000
#define DD 128
#define K2 256
#define NMAX 100000
#define AGG4 ((size_t)NMAX * DD / 4)

#define CDIV(a,b) (((a)+(b)-1)/(b))

// ---------------- scratch ----------------
__device__ float4 g_agg_t[2 * AGG4];
__device__ float4 g_agg_m[2 * AGG4];
__device__ float4 g_bm0[AGG4];
__device__ float4 g_bm1[AGG4];
__device__ float4 g_bt0[AGG4];
__device__ float4 g_bt1[AGG4];
__device__ float4 g_inv_t[NT / 4];
__device__ float4 g_inv_m[NM / 4];
__device__ float4 g_Bext[3 * 2 * K2 * DD / 4];   // tf32 bits [lt][k][j]
__device__ int    g_e32_mt[2 * NE];
__device__ int    g_e32_tm[2 * NE];
__device__ int    g_is32;

__device__ __forceinline__ uint32_t f2tf32(float f) {
    uint32_t r;
    asm("cvt.rna.tf32.f32 %0, %1;" : "=r"(r) : "f"(f));
    return r;
}
__device__ __forceinline__ uint32_t smem_u32(const void* p) {
    uint32_t a;
    asm("{ .reg .u64 t; cvta.to.shared.u64 t, %1; cvt.u32.u64 %0, t; }" : "=r"(a) : "l"(p));
    return a;
}

// ---------------- preproc kernels ----------------
__global__ void detect_reset() { g_is32 = 0; }
__global__ void detect_kernel(const unsigned* __restrict__ p) {
    int i = blockIdx.x * blockDim.x + threadIdx.x;
    unsigned v = 0;
    for (int w = i * 2 + 1; w < 2 * NE; w += gridDim.x * blockDim.x * 2) v |= p[w];
    if (__syncthreads_or(v != 0) && threadIdx.x == 0) atomicExch(&g_is32, 1);
}
__global__ void convert_count(const void* __restrict__ e, int* __restrict__ out,
                              float* __restrict__ cnt) {
    int i = blockIdx.x * blockDim.x + threadIdx.x;
    if (i >= 2 * NE) return;
    int v;
    if (g_is32) v = ((const int*)e)[i];
    else        v = (int)((const long long*)e)[i];
    v = min(max(v, 0), NMAX - 1);
    out[i] = v;
    if (i >= NE) atomicAdd(&cnt[v], 1.0f);
}
__global__ void invert_kernel(float* __restrict__ c, int n) {
    int i = blockIdx.x * blockDim.x + threadIdx.x;
    if (i < n) c[i] = 1.0f / fmaxf(c[i], 1.0f);
}
__global__ void zero4(float4* a, int na, float4* b, int nb,
                      float4* c, int nc, float4* d, int nd) {
    int i = blockIdx.x * blockDim.x + threadIdx.x;
    int stride = gridDim.x * blockDim.x;
    float4 z = make_float4(0.f, 0.f, 0.f, 0.f);
    for (int k = i; k < na; k += stride) a[k] = z;
    for (int k = i; k < nb; k += stride) b[k] = z;
    for (int k = i; k < nc; k += stride) c[k] = z;
    for (int k = i; k < nd; k += stride) d[k] = z;
}
__global__ void zero_two(float4* p0, int n0, float4* p1, int n1) {
    int i = blockIdx.x * blockDim.x + threadIdx.x;
    int stride = gridDim.x * blockDim.x;
    float4 z = make_float4(0.f, 0.f, 0.f, 0.f);
    for (int k = i; k < n0; k += stride) p0[k] = z;
    for (int k = i; k < n1; k += stride) p1[k] = z;
}
__global__ void zero_kernel(float4* p, int n4) {
    int i = blockIdx.x * blockDim.x + threadIdx.x;
    int stride = gridDim.x * blockDim.x;
    float4 z = make_float4(0.f, 0.f, 0.f, 0.f);
    for (; i < n4; i += stride) p[i] = z;
}
__global__ void prep_weights(const float* __restrict__ Wl,
                             const float* __restrict__ Wr,
                             uint32_t* __restrict__ Bext) {
    int i = blockIdx.x * blockDim.x + threadIdx.x;
    if (i >= 3 * 2 * K2 * DD) return;
    int j  = i % DD;
    int k  = (i / DD) % K2;
    int lt = i / (DD * K2);
    float v = (k < DD) ? Wl[((size_t)lt * DD + j) * DD + k]
                       : Wr[((size_t)lt * DD + j) * DD + (k - DD)];
    Bext[i] = f2tf32(v);
}

// ---------------- scatter via TMA bulk-reduce, inv pre-scaled ----------------
#define EPW 4
__global__ void __launch_bounds__(256)
scatter_bulk(const float* __restrict__ xsrc, const int* __restrict__ edge,
             const float* __restrict__ inv, float* __restrict__ agg) {
    __shared__ __align__(16) float smem[8][EPW][DD];
    const int wInB = threadIdx.x >> 5;
    const int lane = threadIdx.x & 31;
    const int gw = (blockIdx.x * blockDim.x + threadIdx.x) >> 5;
    const int base = gw * EPW;
    if (base >= NE) return;
    const int nE = min(EPW, NE - base);
    const float4* X = (const float4*)xsrc;

#pragma unroll
    for (int j = 0; j < EPW; j++) {
        if (j < nE) {
            int src = edge[base + j];
            float s = inv[edge[NE + base + j]];
            float4 v = X[(size_t)src * (DD / 4) + lane];
            ((float4*)smem[wInB][j])[lane] =
                make_float4(v.x * s, v.y * s, v.z * s, v.w * s);
        }
    }
    __syncwarp();
    if (lane == 0) {
        asm volatile("fence.proxy.async.shared::cta;" ::: "memory");
#pragma unroll
        for (int j = 0; j < EPW; j++) {
            if (j < nE) {
                int dst = edge[NE + base + j];
                float* gp = agg + (size_t)dst * DD;
                uint32_t sa = smem_u32(&smem[wInB][j][0]);
                asm volatile(
                    "cp.reduce.async.bulk.global.shared::cta.bulk_group.add.f32 "
                    "[%0], [%1], %2;" :: "l"(gp), "r"(sa), "r"(DD * 4) : "memory");
            }
        }
        asm volatile("cp.async.bulk.commit_group;" ::: "memory");
        asm volatile("cp.async.bulk.wait_group 0;" ::: "memory");
    }
}

// ---------------- tf32 mma.sync GEMM, permuted smem + v4 fragment loads ----
// As[k][p(r)], p(r) = (r&7)*16 + (r>>3);  Bs[k][q(c)], q(c) = (c&7)*16 + (c>>3)
// Inner loop: 6 x ld.shared.v4 per 16 MMAs (was 24 scalar LDS).
__global__ void __launch_bounds__(256)
gemm_sage_tc(const float* __restrict__ Aagg,
             const float* __restrict__ Xdst, const uint32_t* __restrict__ B,
             const float* __restrict__ bias, float* __restrict__ Cout,
             int nRows, int relu) {
    __shared__ __align__(16) uint32_t As[32][140];
    __shared__ __align__(16) uint32_t Bs[32][140];

    const int tid  = threadIdx.x;
    const int wid  = tid >> 5;
    const int lane = tid & 31;
    const int g    = lane >> 2;
    const int t    = lane & 3;
    const int m0   = (wid & 1) * 64;
    const int n0   = (wid >> 1) * 32;
    const int mOff = (wid & 1) * 8;      // m0/8
    const int nOff = (wid >> 1) * 4;     // n0/8
    const int rowBase = blockIdx.x * 128;

    float acc[4][4][4];
#pragma unroll
    for (int im = 0; im < 4; im++)
#pragma unroll
        for (int in = 0; in < 4; in++)
#pragma unroll
            for (int q = 0; q < 4; q++) acc[im][in][q] = 0.f;

    for (int kt = 0; kt < K2; kt += 32) {
        // ---- A fill: 128 rows x 32 k ----
#pragma unroll
        for (int p = 0; p < 4; p++) {
            int f = tid + p * 256;
            int r = f >> 3;
            int q = f & 7;
            int gr = rowBase + r;
            if (gr >= nRows) gr = nRows - 1;
            int kg = kt + q * 4;
            const float* src = (kg < DD) ? (Aagg + (size_t)gr * DD + kg)
                                         : (Xdst + (size_t)gr * DD + (kg - DD));
            float4 v = *(const float4*)src;
            int pr = (r & 7) * 16 + (r >> 3);
            As[q * 4 + 0][pr] = f2tf32(v.x);
            As[q * 4 + 1][pr] = f2tf32(v.y);
            As[q * 4 + 2][pr] = f2tf32(v.z);
            As[q * 4 + 3][pr] = f2tf32(v.w);
        }
        // ---- B fill: 32 k x 128 cols (already tf32 bits) ----
#pragma unroll
        for (int p = 0; p < 4; p++) {
            int f = tid + p * 256;
            int kr = f >> 5;
            int c4 = f & 31;
            uint4 rb = *(const uint4*)(B + (size_t)(kt + kr) * DD + c4 * 4);
            int c = c4 * 4;
            Bs[kr][((c + 0) & 7) * 16 + ((c + 0) >> 3)] = rb.x;
            Bs[kr][((c + 1) & 7) * 16 + ((c + 1) >> 3)] = rb.y;
            Bs[kr][((c + 2) & 7) * 16 + ((c + 2) >> 3)] = rb.z;
            Bs[kr][((c + 3) & 7) * 16 + ((c + 3) >> 3)] = rb.w;
        }
        __syncthreads();

#pragma unroll
        for (int kk = 0; kk < 32; kk += 8) {
            const uint32_t* A0 = &As[kk + t][g * 16 + mOff];
            const uint32_t* A1 = &As[kk + t + 4][g * 16 + mOff];
            uint4 va0 = *(const uint4*)A0;        // a[0][0],a[0][1],a[1][0],a[1][1]
            uint4 va1 = *(const uint4*)(A0 + 4);  // a[2][0],a[2][1],a[3][0],a[3][1]
            uint4 vb0 = *(const uint4*)A1;        // a[0][2],a[0][3],a[1][2],a[1][3]
            uint4 vb1 = *(const uint4*)(A1 + 4);
            uint4 w0 = *(const uint4*)&Bs[kk + t][g * 16 + nOff];      // b[in][0]
            uint4 w1 = *(const uint4*)&Bs[kk + t + 4][g * 16 + nOff];  // b[in][1]

            uint32_t a[4][4];
            a[0][0] = va0.x; a[0][1] = va0.y; a[0][2] = vb0.x; a[0][3] = vb0.y;
            a[1][0] = va0.z; a[1][1] = va0.w; a[1][2] = vb0.z; a[1][3] = vb0.w;
            a[2][0] = va1.x; a[2][1] = va1.y; a[2][2] = vb1.x; a[2][3] = vb1.y;
            a[3][0] = va1.z; a[3][1] = va1.w; a[3][2] = vb1.z; a[3][3] = vb1.w;
            uint32_t b[4][2];
            b[0][0] = w0.x; b[1][0] = w0.y; b[2][0] = w0.z; b[3][0] = w0.w;
            b[0][1] = w1.x; b[1][1] = w1.y; b[2][1] = w1.z; b[3][1] = w1.w;

#pragma unroll
            for (int im = 0; im < 4; im++)
#pragma unroll
                for (int in = 0; in < 4; in++) {
                    asm volatile(
                        "mma.sync.aligned.m16n8k8.row.col.f32.tf32.tf32.f32 "
                        "{%0,%1,%2,%3}, {%4,%5,%6,%7}, {%8,%9}, {%0,%1,%2,%3};"
                        : "+f"(acc[im][in][0]), "+f"(acc[im][in][1]),
                          "+f"(acc[im][in][2]), "+f"(acc[im][in][3])
                        : "r"(a[im][0]), "r"(a[im][1]), "r"(a[im][2]), "r"(a[im][3]),
                          "r"(b[in][0]), "r"(b[in][1]));
                }
        }
        __syncthreads();
    }

#pragma unroll
    for (int in = 0; in < 4; in++) {
        int col = n0 + in * 8 + 2 * t;
        float b0 = bias[col], b1 = bias[col + 1];
#pragma unroll
        for (int im = 0; im < 4; im++) {
            int r0 = rowBase + m0 + im * 16 + g;
            float v0 = acc[im][in][0] + b0;
            float v1 = acc[im][in][1] + b1;
            float v2 = acc[im][in][2] + b0;
            float v3 = acc[im][in][3] + b1;
            if (relu) {
                v0 = fmaxf(v0, 0.f); v1 = fmaxf(v1, 0.f);
                v2 = fmaxf(v2, 0.f); v3 = fmaxf(v3, 0.f);
            }
            if (r0 < nRows)
                *(float2*)(Cout + (size_t)r0 * DD + col) = make_float2(v0, v1);
            if (r0 + 8 < nRows)
                *(float2*)(Cout + (size_t)(r0 + 8) * DD + col) = make_float2(v2, v3);
        }
    }
}

// ---------------- launch ----------------
extern "C" void kernel_launch(void* const* d_in, const int* in_sizes, int n_in,
                              void* d_out, int out_size) {
    static bool s_init = false;
    static cudaStream_t sT, sM;
    static cudaEvent_t evDet, evO, evZ1, evGT[3], evGM[3];
    if (!s_init) {
        cudaStreamCreateWithFlags(&sT, cudaStreamNonBlocking);
        cudaStreamCreateWithFlags(&sM, cudaStreamNonBlocking);
        cudaEventCreateWithFlags(&evDet, cudaEventDisableTiming);
        cudaEventCreateWithFlags(&evO, cudaEventDisableTiming);
        cudaEventCreateWithFlags(&evZ1, cudaEventDisableTiming);
        for (int i = 0; i < 3; i++) {
            cudaEventCreateWithFlags(&evGT[i], cudaEventDisableTiming);
            cudaEventCreateWithFlags(&evGM[i], cudaEventDisableTiming);
        }
        s_init = true;
    }

    const float* x_m = (const float*)d_in[0];
    const float* x_t = (const float*)d_in[1];
    const float* Wl  = (const float*)d_in[2];
    const float* bl  = (const float*)d_in[3];
    const float* Wr  = (const float*)d_in[4];
    const void*  e_mt = d_in[5];
    const void*  e_tm = d_in[6];
    float* out = (float*)d_out;

    float *agg_t, *agg_m, *bm0, *bm1, *bt0, *bt1, *inv_t, *inv_m;
    uint32_t* Bext;
    int *e32_mt, *e32_tm;
    cudaGetSymbolAddress((void**)&agg_t, g_agg_t);
    cudaGetSymbolAddress((void**)&agg_m, g_agg_m);
    cudaGetSymbolAddress((void**)&bm0, g_bm0);
    cudaGetSymbolAddress((void**)&bm1, g_bm1);
    cudaGetSymbolAddress((void**)&bt0, g_bt0);
    cudaGetSymbolAddress((void**)&bt1, g_bt1);
    cudaGetSymbolAddress((void**)&inv_t, g_inv_t);
    cudaGetSymbolAddress((void**)&inv_m, g_inv_m);
    cudaGetSymbolAddress((void**)&Bext, g_Bext);
    cudaGetSymbolAddress((void**)&e32_mt, g_e32_mt);
    cudaGetSymbolAddress((void**)&e32_tm, g_e32_tm);

    const int scatterBlocks = CDIV(CDIV(NE, EPW) * 32, 256);
    const int agg4 = (int)AGG4;
    float* aggT[2] = { agg_t, agg_t + AGG4 * 4 };
    float* aggM[2] = { agg_m, agg_m + AGG4 * 4 };

    // ---- origin stream: track-side preproc; launch #6 = scatter_bulk (ncu) --
    detect_reset<<<1, 1>>>();                                             // 1
    zero4<<<4096, 256>>>((float4*)inv_t, NT / 4, (float4*)inv_m, NM / 4,  // 2
                         (float4*)aggT[0], agg4, (float4*)aggM[0], agg4);
    detect_kernel<<<256, 256>>>((const unsigned*)e_mt);                   // 3
    cudaEventRecord(evDet, 0);
    convert_count<<<CDIV(2 * NE, 256), 256>>>(e_mt, e32_mt, (float*)inv_t); // 4
    invert_kernel<<<CDIV(NT, 256), 256>>>((float*)inv_t, NT);             // 5
    scatter_bulk<<<scatterBlocks, 256>>>(x_m, e32_mt, (float*)inv_t, aggT[0]); // 6
    prep_weights<<<CDIV(3 * 2 * K2 * DD, 256), 256>>>(Wl, Wr, Bext);      // 7
    cudaEventRecord(evO, 0);

    // ---- stream M: musician-side preproc + buf1 zeros ----
    cudaStreamWaitEvent(sM, evDet, 0);
    convert_count<<<CDIV(2 * NE, 256), 256, 0, sM>>>(e_tm, e32_tm, (float*)inv_m);
    invert_kernel<<<CDIV(NM, 256), 256, 0, sM>>>((float*)inv_m, NM);
    zero_two<<<2048, 256, 0, sM>>>((float4*)aggT[1], agg4, (float4*)aggM[1], agg4);
    cudaEventRecord(evZ1, sM);
    scatter_bulk<<<scatterBlocks, 256, 0, sM>>>(x_t, e32_tm, (float*)inv_m, aggM[0]);
    cudaStreamWaitEvent(sM, evO, 0);
    // layer 0, musician chain
    gemm_sage_tc<<<CDIV(NM, 128), 256, 0, sM>>>(
        aggM[0], x_m, Bext + (size_t)1 * K2 * DD, bl + (size_t)1 * DD, bm0, NM, 1);
    cudaEventRecord(evGM[0], sM);
    zero_kernel<<<2048, 256, 0, sM>>>((float4*)aggM[0], agg4);  // re-zero for layer 2

    // ---- stream T: layer 0, track chain ----
    cudaStreamWaitEvent(sT, evO, 0);
    gemm_sage_tc<<<CDIV(NT, 128), 256, 0, sT>>>(
        aggT[0], x_t, Bext + (size_t)0 * K2 * DD, bl + (size_t)0 * DD, bt0, NT, 1);
    cudaEventRecord(evGT[0], sT);
    zero_kernel<<<2048, 256, 0, sT>>>((float4*)aggT[0], agg4);  // re-zero for layer 2

    const float* xm_cur = bm0;
    const float* xt_cur = bt0;
    float* out_m = out;
    float* out_t = out + (size_t)NM * DD;

    for (int layer = 1; layer < 3; layer++) {
        const int b = layer & 1;
        float* xt_next = (layer == 2) ? out_t : bt1;
        float* xm_next = (layer == 2) ? out_m : bm1;
        int relu = (layer < 2) ? 1 : 0;

        // track chain (stream T): needs gemm_M(l-1); buf1 also needs evZ1
        cudaStreamWaitEvent(sT, evGM[layer - 1], 0);
        if (layer == 1) cudaStreamWaitEvent(sT, evZ1, 0);
        scatter_bulk<<<scatterBlocks, 256, 0, sT>>>(xm_cur, e32_mt, (float*)inv_t, aggT[b]);
        gemm_sage_tc<<<CDIV(NT, 128), 256, 0, sT>>>(
            aggT[b], xt_cur,
            Bext + (size_t)(layer * 2 + 0) * K2 * DD,
            bl + (size_t)(layer * 2 + 0) * DD,
            xt_next, NT, relu);
        cudaEventRecord(evGT[layer], sT);

        // musician chain (stream M): needs gemm_T(l-1)
        cudaStreamWaitEvent(sM, evGT[layer - 1], 0);
        scatter_bulk<<<scatterBlocks, 256, 0, sM>>>(xt_cur, e32_tm, (float*)inv_m, aggM[b]);
        gemm_sage_tc<<<CDIV(NM, 128), 256, 0, sM>>>(
            aggM[b], xm_cur,
            Bext + (size_t)(layer * 2 + 1) * K2 * DD,
            bl + (size_t)(layer * 2 + 1) * DD,
            xm_next, NM, relu);
        cudaEventRecord(evGM[layer], sM);

        xm_cur = xm_next;
        xt_cur = xt_next;
    }

    cudaStreamWaitEvent(0, evGT[2], 0);
    cudaStreamWaitEvent(0, evGM[2], 0);
}

// round 14
// speedup vs baseline: 1.5018x; 1.5018x over previous
#include <cuda_runtime.h>
#include <cstdint>

// Problem constants
#define NM 100000
#define NT 100000
#define NE 400000
#define DD 128
#define K2 256
#define NMAX 100000
#define AGG4 ((size_t)NMAX * DD / 4)

#define CDIV(a,b) (((a)+(b)-1)/(b))

// ---------------- scratch ----------------
__device__ float4 g_agg_t[2 * AGG4];
__device__ float4 g_agg_m[2 * AGG4];
__device__ float4 g_bm0[AGG4];
__device__ float4 g_bm1[AGG4];
__device__ float4 g_bt0[AGG4];
__device__ float4 g_bt1[AGG4];
__device__ float4 g_inv_t[NT / 4];
__device__ float4 g_inv_m[NM / 4];
__device__ float4 g_Bext[3 * 2 * K2 * DD / 4];   // tf32 bits [lt][k][j]
__device__ int    g_e32_mt[2 * NE];
__device__ int    g_e32_tm[2 * NE];
__device__ int    g_is32 = 0;   // static init; int64 data never writes it,
                                // int32 data idempotently sets 1 every run

__device__ __forceinline__ uint32_t f2tf32(float f) {
    uint32_t r;
    asm("cvt.rna.tf32.f32 %0, %1;" : "=r"(r) : "f"(f));
    return r;
}
__device__ __forceinline__ uint32_t smem_u32(const void* p) {
    uint32_t a;
    asm("{ .reg .u64 t; cvta.to.shared.u64 t, %1; cvt.u32.u64 %0, t; }" : "=r"(a) : "l"(p));
    return a;
}

// ---------------- preproc kernels ----------------
__global__ void detect_kernel(const unsigned* __restrict__ p) {
    int i = blockIdx.x * blockDim.x + threadIdx.x;
    unsigned v = 0;
    for (int w = i * 2 + 1; w < 2 * NE; w += gridDim.x * blockDim.x * 2) v |= p[w];
    if (__syncthreads_or(v != 0) && threadIdx.x == 0) atomicExch(&g_is32, 1);
}
__global__ void convert_count(const void* __restrict__ e, int* __restrict__ out,
                              float* __restrict__ cnt) {
    int i = blockIdx.x * blockDim.x + threadIdx.x;
    if (i >= 2 * NE) return;
    int v;
    if (g_is32) v = ((const int*)e)[i];
    else        v = (int)((const long long*)e)[i];
    v = min(max(v, 0), NMAX - 1);
    out[i] = v;
    if (i >= NE) atomicAdd(&cnt[v], 1.0f);
}
__global__ void invert_kernel(float* __restrict__ c, int n) {
    int i = blockIdx.x * blockDim.x + threadIdx.x;
    if (i < n) c[i] = 1.0f / fmaxf(c[i], 1.0f);
}
__global__ void zero4(float4* a, int na, float4* b, int nb,
                      float4* c, int nc, float4* d, int nd) {
    int i = blockIdx.x * blockDim.x + threadIdx.x;
    int stride = gridDim.x * blockDim.x;
    float4 z = make_float4(0.f, 0.f, 0.f, 0.f);
    for (int k = i; k < na; k += stride) a[k] = z;
    for (int k = i; k < nb; k += stride) b[k] = z;
    for (int k = i; k < nc; k += stride) c[k] = z;
    for (int k = i; k < nd; k += stride) d[k] = z;
}
__global__ void zero_two(float4* p0, int n0, float4* p1, int n1) {
    int i = blockIdx.x * blockDim.x + threadIdx.x;
    int stride = gridDim.x * blockDim.x;
    float4 z = make_float4(0.f, 0.f, 0.f, 0.f);
    for (int k = i; k < n0; k += stride) p0[k] = z;
    for (int k = i; k < n1; k += stride) p1[k] = z;
}
__global__ void zero_kernel(float4* p, int n4) {
    int i = blockIdx.x * blockDim.x + threadIdx.x;
    int stride = gridDim.x * blockDim.x;
    float4 z = make_float4(0.f, 0.f, 0.f, 0.f);
    for (; i < n4; i += stride) p[i] = z;
}
__global__ void prep_weights(const float* __restrict__ Wl,
                             const float* __restrict__ Wr,
                             uint32_t* __restrict__ Bext) {
    int i = blockIdx.x * blockDim.x + threadIdx.x;
    if (i >= 3 * 2 * K2 * DD) return;
    int j  = i % DD;
    int k  = (i / DD) % K2;
    int lt = i / (DD * K2);
    float v = (k < DD) ? Wl[((size_t)lt * DD + j) * DD + k]
                       : Wr[((size_t)lt * DD + j) * DD + (k - DD)];
    Bext[i] = f2tf32(v);
}

// ---------------- scatter via TMA bulk-reduce (no inv; gemm scales) --------
#define EPW 4
__global__ void __launch_bounds__(256)
scatter_bulk(const float* __restrict__ xsrc, const int* __restrict__ edge,
             float* __restrict__ agg) {
    __shared__ __align__(16) float smem[8][EPW][DD];
    const int wInB = threadIdx.x >> 5;
    const int lane = threadIdx.x & 31;
    const int gw = (blockIdx.x * blockDim.x + threadIdx.x) >> 5;
    const int base = gw * EPW;
    if (base >= NE) return;
    const int nE = min(EPW, NE - base);
    const float4* X = (const float4*)xsrc;

#pragma unroll
    for (int j = 0; j < EPW; j++) {
        if (j < nE) {
            int src = edge[base + j];
            ((float4*)smem[wInB][j])[lane] = X[(size_t)src * (DD / 4) + lane];
        }
    }
    __syncwarp();
    if (lane == 0) {
        asm volatile("fence.proxy.async.shared::cta;" ::: "memory");
#pragma unroll
        for (int j = 0; j < EPW; j++) {
            if (j < nE) {
                int dst = edge[NE + base + j];
                float* gp = agg + (size_t)dst * DD;
                uint32_t sa = smem_u32(&smem[wInB][j][0]);
                asm volatile(
                    "cp.reduce.async.bulk.global.shared::cta.bulk_group.add.f32 "
                    "[%0], [%1], %2;" :: "l"(gp), "r"(sa), "r"(DD * 4) : "memory");
            }
        }
        asm volatile("cp.async.bulk.commit_group;" ::: "memory");
        asm volatile("cp.async.bulk.wait_group 0;" ::: "memory");
    }
}

// ---------------- tf32 mma.sync GEMM (R9-proven; inv in A-load, B tf32) ----
__global__ void __launch_bounds__(256)
gemm_sage_tc(const float* __restrict__ Aagg, const float* __restrict__ inv,
             const float* __restrict__ Xdst, const uint32_t* __restrict__ B,
             const float* __restrict__ bias, float* __restrict__ Cout,
             int nRows, int relu) {
    __shared__ uint32_t As[128][36];
    __shared__ uint32_t Bs[32][136];

    const int tid  = threadIdx.x;
    const int wid  = tid >> 5;
    const int lane = tid & 31;
    const int g    = lane >> 2;
    const int t    = lane & 3;
    const int m0   = (wid & 1) * 64;
    const int n0   = (wid >> 1) * 32;
    const int rowBase = blockIdx.x * 128;

    float acc[4][4][4];
#pragma unroll
    for (int im = 0; im < 4; im++)
#pragma unroll
        for (int in = 0; in < 4; in++)
#pragma unroll
            for (int q = 0; q < 4; q++) acc[im][in][q] = 0.f;

    for (int kt = 0; kt < K2; kt += 32) {
#pragma unroll
        for (int p = 0; p < 4; p++) {
            int f = tid + p * 256;
            int r = f >> 3;
            int q = f & 7;
            int gr = rowBase + r;
            if (gr >= nRows) gr = nRows - 1;
            int kg = kt + q * 4;
            float s;
            const float* src;
            if (kg < DD) { src = Aagg + (size_t)gr * DD + kg; s = inv[gr]; }
            else         { src = Xdst + (size_t)gr * DD + (kg - DD); s = 1.0f; }
            float4 v = *(const float4*)src;
            As[r][q * 4 + 0] = f2tf32(v.x * s);
            As[r][q * 4 + 1] = f2tf32(v.y * s);
            As[r][q * 4 + 2] = f2tf32(v.z * s);
            As[r][q * 4 + 3] = f2tf32(v.w * s);
        }
#pragma unroll
        for (int p = 0; p < 4; p++) {
            int f = tid + p * 256;
            int kr = f >> 5;
            int c  = f & 31;
            *(uint4*)&Bs[kr][c * 4] = *(const uint4*)(B + (size_t)(kt + kr) * DD + c * 4);
        }
        __syncthreads();

#pragma unroll
        for (int kk = 0; kk < 32; kk += 8) {
            uint32_t a[4][4], b[4][2];
#pragma unroll
            for (int im = 0; im < 4; im++) {
                int rm = m0 + im * 16 + g;
                a[im][0] = As[rm][kk + t];
                a[im][1] = As[rm + 8][kk + t];
                a[im][2] = As[rm][kk + t + 4];
                a[im][3] = As[rm + 8][kk + t + 4];
            }
#pragma unroll
            for (int in = 0; in < 4; in++) {
                int cn = n0 + in * 8 + g;
                b[in][0] = Bs[kk + t][cn];
                b[in][1] = Bs[kk + t + 4][cn];
            }
#pragma unroll
            for (int im = 0; im < 4; im++)
#pragma unroll
                for (int in = 0; in < 4; in++) {
                    asm volatile(
                        "mma.sync.aligned.m16n8k8.row.col.f32.tf32.tf32.f32 "
                        "{%0,%1,%2,%3}, {%4,%5,%6,%7}, {%8,%9}, {%0,%1,%2,%3};"
                        : "+f"(acc[im][in][0]), "+f"(acc[im][in][1]),
                          "+f"(acc[im][in][2]), "+f"(acc[im][in][3])
                        : "r"(a[im][0]), "r"(a[im][1]), "r"(a[im][2]), "r"(a[im][3]),
                          "r"(b[in][0]), "r"(b[in][1]));
                }
        }
        __syncthreads();
    }

#pragma unroll
    for (int in = 0; in < 4; in++) {
        int col = n0 + in * 8 + 2 * t;
        float b0 = bias[col], b1 = bias[col + 1];
#pragma unroll
        for (int im = 0; im < 4; im++) {
            int r0 = rowBase + m0 + im * 16 + g;
            float v0 = acc[im][in][0] + b0;
            float v1 = acc[im][in][1] + b1;
            float v2 = acc[im][in][2] + b0;
            float v3 = acc[im][in][3] + b1;
            if (relu) {
                v0 = fmaxf(v0, 0.f); v1 = fmaxf(v1, 0.f);
                v2 = fmaxf(v2, 0.f); v3 = fmaxf(v3, 0.f);
            }
            if (r0 < nRows)
                *(float2*)(Cout + (size_t)r0 * DD + col) = make_float2(v0, v1);
            if (r0 + 8 < nRows)
                *(float2*)(Cout + (size_t)(r0 + 8) * DD + col) = make_float2(v2, v3);
        }
    }
}

// ---------------- launch ----------------
extern "C" void kernel_launch(void* const* d_in, const int* in_sizes, int n_in,
                              void* d_out, int out_size) {
    static bool s_init = false;
    static cudaStream_t sM;
    static cudaEvent_t evZ, evDet, evPrep, evZ1, evGT[3], evGM[3];
    if (!s_init) {
        cudaStreamCreateWithFlags(&sM, cudaStreamNonBlocking);
        cudaEventCreateWithFlags(&evZ, cudaEventDisableTiming);
        cudaEventCreateWithFlags(&evDet, cudaEventDisableTiming);
        cudaEventCreateWithFlags(&evPrep, cudaEventDisableTiming);
        cudaEventCreateWithFlags(&evZ1, cudaEventDisableTiming);
        for (int i = 0; i < 3; i++) {
            cudaEventCreateWithFlags(&evGT[i], cudaEventDisableTiming);
            cudaEventCreateWithFlags(&evGM[i], cudaEventDisableTiming);
        }
        s_init = true;
    }

    const float* x_m = (const float*)d_in[0];
    const float* x_t = (const float*)d_in[1];
    const float* Wl  = (const float*)d_in[2];
    const float* bl  = (const float*)d_in[3];
    const float* Wr  = (const float*)d_in[4];
    const void*  e_mt = d_in[5];
    const void*  e_tm = d_in[6];
    float* out = (float*)d_out;

    float *agg_t, *agg_m, *bm0, *bm1, *bt0, *bt1, *inv_t, *inv_m;
    uint32_t* Bext;
    int *e32_mt, *e32_tm;
    cudaGetSymbolAddress((void**)&agg_t, g_agg_t);
    cudaGetSymbolAddress((void**)&agg_m, g_agg_m);
    cudaGetSymbolAddress((void**)&bm0, g_bm0);
    cudaGetSymbolAddress((void**)&bm1, g_bm1);
    cudaGetSymbolAddress((void**)&bt0, g_bt0);
    cudaGetSymbolAddress((void**)&bt1, g_bt1);
    cudaGetSymbolAddress((void**)&inv_t, g_inv_t);
    cudaGetSymbolAddress((void**)&inv_m, g_inv_m);
    cudaGetSymbolAddress((void**)&Bext, g_Bext);
    cudaGetSymbolAddress((void**)&e32_mt, g_e32_mt);
    cudaGetSymbolAddress((void**)&e32_tm, g_e32_tm);

    const int scatterBlocks = CDIV(CDIV(NE, EPW) * 32, 256);
    const int agg4 = (int)AGG4;
    float* aggT[2] = { agg_t, agg_t + AGG4 * 4 };
    float* aggM[2] = { agg_m, agg_m + AGG4 * 4 };
    float* out_m = out;
    float* out_t = out + (size_t)NM * DD;

    // ---- origin stream (track chain). Launch index 3 = scatter_bulk (ncu) --
    zero4<<<4096, 256>>>((float4*)inv_t, NT / 4, (float4*)inv_m, NM / 4,      // 0
                         (float4*)aggT[0], agg4, (float4*)aggM[0], agg4);
    cudaEventRecord(evZ, 0);
    detect_kernel<<<256, 256>>>((const unsigned*)e_mt);                        // 1
    cudaEventRecord(evDet, 0);
    convert_count<<<CDIV(2 * NE, 256), 256>>>(e_mt, e32_mt, (float*)inv_t);    // 2
    scatter_bulk<<<scatterBlocks, 256>>>(x_m, e32_mt, aggT[0]);                // 3 <- ncu
    invert_kernel<<<CDIV(NT, 256), 256>>>((float*)inv_t, NT);                  // 4
    prep_weights<<<CDIV(3 * 2 * K2 * DD, 256), 256>>>(Wl, Wr, Bext);           // 5
    cudaEventRecord(evPrep, 0);
    // layer 0, track
    gemm_sage_tc<<<CDIV(NT, 128), 256>>>(
        aggT[0], (float*)inv_t, x_t, Bext + (size_t)0 * K2 * DD,
        bl + (size_t)0 * DD, bt0, NT, 1);
    cudaEventRecord(evGT[0], 0);
    zero_kernel<<<2048, 256>>>((float4*)aggT[0], agg4);   // re-zero for layer 2

    // ---- stream M (musician chain) ----
    cudaStreamWaitEvent(sM, evDet, 0);
    cudaStreamWaitEvent(sM, evZ, 0);
    convert_count<<<CDIV(2 * NE, 256), 256, 0, sM>>>(e_tm, e32_tm, (float*)inv_m);
    invert_kernel<<<CDIV(NM, 256), 256, 0, sM>>>((float*)inv_m, NM);
    zero_two<<<2048, 256, 0, sM>>>((float4*)aggT[1], agg4, (float4*)aggM[1], agg4);
    cudaEventRecord(evZ1, sM);
    scatter_bulk<<<scatterBlocks, 256, 0, sM>>>(x_t, e32_tm, aggM[0]);
    cudaStreamWaitEvent(sM, evPrep, 0);
    gemm_sage_tc<<<CDIV(NM, 128), 256, 0, sM>>>(
        aggM[0], (float*)inv_m, x_m, Bext + (size_t)1 * K2 * DD,
        bl + (size_t)1 * DD, bm0, NM, 1);
    cudaEventRecord(evGM[0], sM);
    zero_kernel<<<2048, 256, 0, sM>>>((float4*)aggM[0], agg4);  // re-zero for layer 2

    const float* xm_cur = bm0;
    const float* xt_cur = bt0;

    for (int layer = 1; layer < 3; layer++) {
        const int b = layer & 1;
        float* xt_next = (layer == 2) ? out_t : bt1;
        float* xm_next = (layer == 2) ? out_m : bm1;
        int relu = (layer < 2) ? 1 : 0;

        // track chain (origin): needs gemm_M(l-1) output; buf1 needs evZ1
        cudaStreamWaitEvent(0, evGM[layer - 1], 0);
        if (layer == 1) cudaStreamWaitEvent(0, evZ1, 0);
        scatter_bulk<<<scatterBlocks, 256>>>(xm_cur, e32_mt, aggT[b]);
        gemm_sage_tc<<<CDIV(NT, 128), 256>>>(
            aggT[b], (float*)inv_t, xt_cur,
            Bext + (size_t)(layer * 2 + 0) * K2 * DD,
            bl + (size_t)(layer * 2 + 0) * DD,
            xt_next, NT, relu);
        cudaEventRecord(evGT[layer], 0);

        // musician chain (sM): needs gemm_T(l-1) output
        cudaStreamWaitEvent(sM, evGT[layer - 1], 0);
        scatter_bulk<<<scatterBlocks, 256, 0, sM>>>(xt_cur, e32_tm, aggM[b]);
        gemm_sage_tc<<<CDIV(NM, 128), 256, 0, sM>>>(
            aggM[b], (float*)inv_m, xm_cur,
            Bext + (size_t)(layer * 2 + 1) * K2 * DD,
            bl + (size_t)(layer * 2 + 1) * DD,
            xm_next, NM, relu);
        cudaEventRecord(evGM[layer], sM);

        xm_cur = xm_next;
        xt_cur = xt_next;
    }

    cudaStreamWaitEvent(0, evGM[2], 0);
}

// round 15
// speedup vs baseline: 1.8625x; 1.2402x over previous
#include <cuda_runtime.h>
#include <cuda_fp16.h>
#include <cstdint>

// Problem constants
#define NM 100000
#define NT 100000
#define NE 400000
#define DD 128
#define K2 256
#define KP2 (K2 / 2)     // k-pairs
#define NMAX 100000
#define AGG4 ((size_t)NMAX * DD / 4)

#define CDIV(a,b) (((a)+(b)-1)/(b))

// ---------------- scratch ----------------
__device__ float4 g_agg_t[2 * AGG4];
__device__ float4 g_agg_m[2 * AGG4];
__device__ float4 g_bm0[AGG4];
__device__ float4 g_bm1[AGG4];
__device__ float4 g_bt0[AGG4];
__device__ float4 g_bt1[AGG4];
__device__ float4 g_inv_t[NT / 4];
__device__ float4 g_inv_m[NM / 4];
__device__ float4 g_Bext[3 * 2 * KP2 * DD / 4];  // half2 pairs [lt][kp][j]
__device__ int    g_e32_mt[2 * NE];
__device__ int    g_e32_tm[2 * NE];
__device__ int    g_is32 = 0;   // int64 data never writes; int32 sets 1 idempotently

__device__ __forceinline__ uint32_t smem_u32(const void* p) {
    uint32_t a;
    asm("{ .reg .u64 t; cvta.to.shared.u64 t, %1; cvt.u32.u64 %0, t; }" : "=r"(a) : "l"(p));
    return a;
}
__device__ __forceinline__ uint32_t pack_h2(float lo, float hi) {
    half2 h = __floats2half2_rn(lo, hi);
    return *(uint32_t*)&h;
}

// ---------------- preproc kernels ----------------
__global__ void detect_kernel(const unsigned* __restrict__ p) {
    int i = blockIdx.x * blockDim.x + threadIdx.x;
    unsigned v = 0;
    for (int w = i * 2 + 1; w < 2 * NE; w += gridDim.x * blockDim.x * 2) v |= p[w];
    if (__syncthreads_or(v != 0) && threadIdx.x == 0) atomicExch(&g_is32, 1);
}
__global__ void convert_count(const void* __restrict__ e, int* __restrict__ out,
                              float* __restrict__ cnt) {
    int i = blockIdx.x * blockDim.x + threadIdx.x;
    if (i >= 2 * NE) return;
    int v;
    if (g_is32) v = ((const int*)e)[i];
    else        v = (int)((const long long*)e)[i];
    v = min(max(v, 0), NMAX - 1);
    out[i] = v;
    if (i >= NE) atomicAdd(&cnt[v], 1.0f);
}
__global__ void invert_kernel(float* __restrict__ c, int n) {
    int i = blockIdx.x * blockDim.x + threadIdx.x;
    if (i < n) c[i] = 1.0f / fmaxf(c[i], 1.0f);
}
__global__ void zero4(float4* a, int na, float4* b, int nb,
                      float4* c, int nc, float4* d, int nd) {
    int i = blockIdx.x * blockDim.x + threadIdx.x;
    int stride = gridDim.x * blockDim.x;
    float4 z = make_float4(0.f, 0.f, 0.f, 0.f);
    for (int k = i; k < na; k += stride) a[k] = z;
    for (int k = i; k < nb; k += stride) b[k] = z;
    for (int k = i; k < nc; k += stride) c[k] = z;
    for (int k = i; k < nd; k += stride) d[k] = z;
}
__global__ void zero_two(float4* p0, int n0, float4* p1, int n1) {
    int i = blockIdx.x * blockDim.x + threadIdx.x;
    int stride = gridDim.x * blockDim.x;
    float4 z = make_float4(0.f, 0.f, 0.f, 0.f);
    for (int k = i; k < n0; k += stride) p0[k] = z;
    for (int k = i; k < n1; k += stride) p1[k] = z;
}
__global__ void zero_kernel(float4* p, int n4) {
    int i = blockIdx.x * blockDim.x + threadIdx.x;
    int stride = gridDim.x * blockDim.x;
    float4 z = make_float4(0.f, 0.f, 0.f, 0.f);
    for (; i < n4; i += stride) p[i] = z;
}
// Bext[lt][kp][j] = half2( W[2kp][j], W[2kp+1][j] ), W = [Wl | Wr] along k
__global__ void prep_weights(const float* __restrict__ Wl,
                             const float* __restrict__ Wr,
                             uint32_t* __restrict__ Bext) {
    int i = blockIdx.x * blockDim.x + threadIdx.x;
    if (i >= 3 * 2 * KP2 * DD) return;
    int j  = i % DD;
    int kp = (i / DD) % KP2;
    int lt = i / (DD * KP2);
    int k0 = 2 * kp;
    float v0, v1;
    if (k0 < DD) {
        v0 = Wl[((size_t)lt * DD + j) * DD + k0];
        v1 = Wl[((size_t)lt * DD + j) * DD + k0 + 1];
    } else {
        v0 = Wr[((size_t)lt * DD + j) * DD + (k0 - DD)];
        v1 = Wr[((size_t)lt * DD + j) * DD + (k0 - DD + 1)];
    }
    Bext[i] = pack_h2(v0, v1);
}

// ---------------- scatter via TMA bulk-reduce ----------------
#define EPW 4
__global__ void __launch_bounds__(256)
scatter_bulk(const float* __restrict__ xsrc, const int* __restrict__ edge,
             float* __restrict__ agg) {
    __shared__ __align__(16) float smem[8][EPW][DD];
    const int wInB = threadIdx.x >> 5;
    const int lane = threadIdx.x & 31;
    const int gw = (blockIdx.x * blockDim.x + threadIdx.x) >> 5;
    const int base = gw * EPW;
    if (base >= NE) return;
    const int nE = min(EPW, NE - base);
    const float4* X = (const float4*)xsrc;

#pragma unroll
    for (int j = 0; j < EPW; j++) {
        if (j < nE) {
            int src = edge[base + j];
            ((float4*)smem[wInB][j])[lane] = X[(size_t)src * (DD / 4) + lane];
        }
    }
    __syncwarp();
    if (lane == 0) {
        asm volatile("fence.proxy.async.shared::cta;" ::: "memory");
#pragma unroll
        for (int j = 0; j < EPW; j++) {
            if (j < nE) {
                int dst = edge[NE + base + j];
                float* gp = agg + (size_t)dst * DD;
                uint32_t sa = smem_u32(&smem[wInB][j][0]);
                asm volatile(
                    "cp.reduce.async.bulk.global.shared::cta.bulk_group.add.f32 "
                    "[%0], [%1], %2;" :: "l"(gp), "r"(sa), "r"(DD * 4) : "memory");
            }
        }
        asm volatile("cp.async.bulk.commit_group;" ::: "memory");
        asm volatile("cp.async.bulk.wait_group 0;" ::: "memory");
    }
}

// ---------------- fp16 mma.sync GEMM (m16n8k16, fp32 accum) ----------------
// C[i,j] = sum_{k<256} Aext[i,k]*W[j,k] + bias[j];  Aext = [agg*inv | x]
// As[r][w]: w = k-pair index within 32-k tile (16 words, stride 20 ->
// frag-load banks (20g+t)%32 all distinct). Bs[kp][col] stride 136 (proven).
__global__ void __launch_bounds__(256)
gemm_sage_tc(const float* __restrict__ Aagg, const float* __restrict__ inv,
             const float* __restrict__ Xdst, const uint32_t* __restrict__ B,
             const float* __restrict__ bias, float* __restrict__ Cout,
             int nRows, int relu) {
    __shared__ uint32_t As[128][20];
    __shared__ uint32_t Bs[16][136];

    const int tid  = threadIdx.x;
    const int wid  = tid >> 5;
    const int lane = tid & 31;
    const int g    = lane >> 2;
    const int t    = lane & 3;
    const int m0   = (wid & 1) * 64;
    const int n0   = (wid >> 1) * 32;
    const int rowBase = blockIdx.x * 128;

    float acc[4][4][4];
#pragma unroll
    for (int im = 0; im < 4; im++)
#pragma unroll
        for (int in = 0; in < 4; in++)
#pragma unroll
            for (int q = 0; q < 4; q++) acc[im][in][q] = 0.f;

    for (int kt = 0; kt < K2; kt += 32) {
        const int ktp = kt >> 1;   // k-pair offset into B
        // ---- A fill: 128 rows x 32 k -> 16 half2 words per row ----
#pragma unroll
        for (int p = 0; p < 4; p++) {
            int f = tid + p * 256;
            int r = f >> 3;
            int q = f & 7;         // float4 index; k = q*4
            int gr = rowBase + r;
            if (gr >= nRows) gr = nRows - 1;
            int kg = kt + q * 4;
            float s;
            const float* src;
            if (kg < DD) { src = Aagg + (size_t)gr * DD + kg; s = inv[gr]; }
            else         { src = Xdst + (size_t)gr * DD + (kg - DD); s = 1.0f; }
            float4 v = *(const float4*)src;
            As[r][q * 2 + 0] = pack_h2(v.x * s, v.y * s);
            As[r][q * 2 + 1] = pack_h2(v.z * s, v.w * s);
        }
        // ---- B fill: 16 k-pairs x 128 cols (pre-packed half2) ----
#pragma unroll
        for (int p = 0; p < 2; p++) {
            int f = tid + p * 256;
            int kp = f >> 5;
            int c4 = f & 31;
            *(uint4*)&Bs[kp][c4 * 4] =
                *(const uint4*)(B + (size_t)(ktp + kp) * DD + c4 * 4);
        }
        __syncthreads();

#pragma unroll
        for (int ks2 = 0; ks2 < 16; ks2 += 8) {   // two k16 steps
            uint32_t a[4][4], b[4][2];
#pragma unroll
            for (int im = 0; im < 4; im++) {
                int rm = m0 + im * 16 + g;
                a[im][0] = As[rm][ks2 + t];
                a[im][1] = As[rm + 8][ks2 + t];
                a[im][2] = As[rm][ks2 + 4 + t];
                a[im][3] = As[rm + 8][ks2 + 4 + t];
            }
#pragma unroll
            for (int in = 0; in < 4; in++) {
                int cn = n0 + in * 8 + g;
                b[in][0] = Bs[ks2 + t][cn];
                b[in][1] = Bs[ks2 + 4 + t][cn];
            }
#pragma unroll
            for (int im = 0; im < 4; im++)
#pragma unroll
                for (int in = 0; in < 4; in++) {
                    asm volatile(
                        "mma.sync.aligned.m16n8k16.row.col.f32.f16.f16.f32 "
                        "{%0,%1,%2,%3}, {%4,%5,%6,%7}, {%8,%9}, {%0,%1,%2,%3};"
                        : "+f"(acc[im][in][0]), "+f"(acc[im][in][1]),
                          "+f"(acc[im][in][2]), "+f"(acc[im][in][3])
                        : "r"(a[im][0]), "r"(a[im][1]), "r"(a[im][2]), "r"(a[im][3]),
                          "r"(b[in][0]), "r"(b[in][1]));
                }
        }
        __syncthreads();
    }

#pragma unroll
    for (int in = 0; in < 4; in++) {
        int col = n0 + in * 8 + 2 * t;
        float b0 = bias[col], b1 = bias[col + 1];
#pragma unroll
        for (int im = 0; im < 4; im++) {
            int r0 = rowBase + m0 + im * 16 + g;
            float v0 = acc[im][in][0] + b0;
            float v1 = acc[im][in][1] + b1;
            float v2 = acc[im][in][2] + b0;
            float v3 = acc[im][in][3] + b1;
            if (relu) {
                v0 = fmaxf(v0, 0.f); v1 = fmaxf(v1, 0.f);
                v2 = fmaxf(v2, 0.f); v3 = fmaxf(v3, 0.f);
            }
            if (r0 < nRows)
                *(float2*)(Cout + (size_t)r0 * DD + col) = make_float2(v0, v1);
            if (r0 + 8 < nRows)
                *(float2*)(Cout + (size_t)(r0 + 8) * DD + col) = make_float2(v2, v3);
        }
    }
}

// ---------------- launch ----------------
extern "C" void kernel_launch(void* const* d_in, const int* in_sizes, int n_in,
                              void* d_out, int out_size) {
    static bool s_init = false;
    static cudaStream_t sM;
    static cudaEvent_t evZ, evDet, evPrep, evZ1, evGT[3], evGM[3];
    if (!s_init) {
        cudaStreamCreateWithFlags(&sM, cudaStreamNonBlocking);
        cudaEventCreateWithFlags(&evZ, cudaEventDisableTiming);
        cudaEventCreateWithFlags(&evDet, cudaEventDisableTiming);
        cudaEventCreateWithFlags(&evPrep, cudaEventDisableTiming);
        cudaEventCreateWithFlags(&evZ1, cudaEventDisableTiming);
        for (int i = 0; i < 3; i++) {
            cudaEventCreateWithFlags(&evGT[i], cudaEventDisableTiming);
            cudaEventCreateWithFlags(&evGM[i], cudaEventDisableTiming);
        }
        s_init = true;
    }

    const float* x_m = (const float*)d_in[0];
    const float* x_t = (const float*)d_in[1];
    const float* Wl  = (const float*)d_in[2];
    const float* bl  = (const float*)d_in[3];
    const float* Wr  = (const float*)d_in[4];
    const void*  e_mt = d_in[5];
    const void*  e_tm = d_in[6];
    float* out = (float*)d_out;

    float *agg_t, *agg_m, *bm0, *bm1, *bt0, *bt1, *inv_t, *inv_m;
    uint32_t* Bext;
    int *e32_mt, *e32_tm;
    cudaGetSymbolAddress((void**)&agg_t, g_agg_t);
    cudaGetSymbolAddress((void**)&agg_m, g_agg_m);
    cudaGetSymbolAddress((void**)&bm0, g_bm0);
    cudaGetSymbolAddress((void**)&bm1, g_bm1);
    cudaGetSymbolAddress((void**)&bt0, g_bt0);
    cudaGetSymbolAddress((void**)&bt1, g_bt1);
    cudaGetSymbolAddress((void**)&inv_t, g_inv_t);
    cudaGetSymbolAddress((void**)&inv_m, g_inv_m);
    cudaGetSymbolAddress((void**)&Bext, g_Bext);
    cudaGetSymbolAddress((void**)&e32_mt, g_e32_mt);
    cudaGetSymbolAddress((void**)&e32_tm, g_e32_tm);

    const int scatterBlocks = CDIV(CDIV(NE, EPW) * 32, 256);
    const int agg4 = (int)AGG4;
    float* aggT[2] = { agg_t, agg_t + AGG4 * 4 };
    float* aggM[2] = { agg_m, agg_m + AGG4 * 4 };
    float* out_m = out;
    float* out_t = out + (size_t)NM * DD;

    // ---- origin stream (track chain). Launch index 3 = scatter_bulk (ncu) --
    zero4<<<4096, 256>>>((float4*)inv_t, NT / 4, (float4*)inv_m, NM / 4,
                         (float4*)aggT[0], agg4, (float4*)aggM[0], agg4);
    cudaEventRecord(evZ, 0);
    detect_kernel<<<256, 256>>>((const unsigned*)e_mt);
    cudaEventRecord(evDet, 0);
    convert_count<<<CDIV(2 * NE, 256), 256>>>(e_mt, e32_mt, (float*)inv_t);
    scatter_bulk<<<scatterBlocks, 256>>>(x_m, e32_mt, aggT[0]);
    invert_kernel<<<CDIV(NT, 256), 256>>>((float*)inv_t, NT);
    prep_weights<<<CDIV(3 * 2 * KP2 * DD, 256), 256>>>(Wl, Wr, Bext);
    cudaEventRecord(evPrep, 0);
    gemm_sage_tc<<<CDIV(NT, 128), 256>>>(
        aggT[0], (float*)inv_t, x_t, Bext + (size_t)0 * KP2 * DD,
        bl + (size_t)0 * DD, bt0, NT, 1);
    cudaEventRecord(evGT[0], 0);
    zero_kernel<<<2048, 256>>>((float4*)aggT[0], agg4);

    // ---- stream M (musician chain) ----
    cudaStreamWaitEvent(sM, evDet, 0);
    cudaStreamWaitEvent(sM, evZ, 0);
    convert_count<<<CDIV(2 * NE, 256), 256, 0, sM>>>(e_tm, e32_tm, (float*)inv_m);
    invert_kernel<<<CDIV(NM, 256), 256, 0, sM>>>((float*)inv_m, NM);
    zero_two<<<2048, 256, 0, sM>>>((float4*)aggT[1], agg4, (float4*)aggM[1], agg4);
    cudaEventRecord(evZ1, sM);
    scatter_bulk<<<scatterBlocks, 256, 0, sM>>>(x_t, e32_tm, aggM[0]);
    cudaStreamWaitEvent(sM, evPrep, 0);
    gemm_sage_tc<<<CDIV(NM, 128), 256, 0, sM>>>(
        aggM[0], (float*)inv_m, x_m, Bext + (size_t)1 * KP2 * DD,
        bl + (size_t)1 * DD, bm0, NM, 1);
    cudaEventRecord(evGM[0], sM);
    zero_kernel<<<2048, 256, 0, sM>>>((float4*)aggM[0], agg4);

    const float* xm_cur = bm0;
    const float* xt_cur = bt0;

    for (int layer = 1; layer < 3; layer++) {
        const int b = layer & 1;
        float* xt_next = (layer == 2) ? out_t : bt1;
        float* xm_next = (layer == 2) ? out_m : bm1;
        int relu = (layer < 2) ? 1 : 0;

        cudaStreamWaitEvent(0, evGM[layer - 1], 0);
        if (layer == 1) cudaStreamWaitEvent(0, evZ1, 0);
        scatter_bulk<<<scatterBlocks, 256>>>(xm_cur, e32_mt, aggT[b]);
        gemm_sage_tc<<<CDIV(NT, 128), 256>>>(
            aggT[b], (float*)inv_t, xt_cur,
            Bext + (size_t)(layer * 2 + 0) * KP2 * DD,
            bl + (size_t)(layer * 2 + 0) * DD,
            xt_next, NT, relu);
        cudaEventRecord(evGT[layer], 0);

        cudaStreamWaitEvent(sM, evGT[layer - 1], 0);
        scatter_bulk<<<scatterBlocks, 256, 0, sM>>>(xt_cur, e32_tm, aggM[b]);
        gemm_sage_tc<<<CDIV(NM, 128), 256, 0, sM>>>(
            aggM[b], (float*)inv_m, xm_cur,
            Bext + (size_t)(layer * 2 + 1) * KP2 * DD,
            bl + (size_t)(layer * 2 + 1) * DD,
            xm_next, NM, relu);
        cudaEventRecord(evGM[layer], sM);

        xm_cur = xm_next;
        xt_cur = xt_next;
    }

    cudaStreamWaitEvent(0, evGM[2], 0);
}